// round 1
// baseline (speedup 1.0000x reference)
#include <cuda_runtime.h>
#include <cuda_bf16.h>

#define NMAX 100000
#define FDIM 128
#define DDIM 32
#define LLEN 100
#define RNUM 5

// Scratch (static device globals — no allocation in kernel_launch)
__device__ float g_proj[NMAX * DDIM];   // features @ W_feat + b_feat, per node
__device__ int   g_skill[NMAX];         // (int)features[n,0]

// ---------------------------------------------------------------------------
// Kernel 1: proj[n,:] = feat[n,:] @ W_feat + b_feat ; skill[n] = (int)feat[n,0]
// Block = 256 threads (8 warps). Tile = 32 rows. Each warp: 4 rows x 32 cols,
// lane = (row_in_4 << 3) | dq ; dq picks a float4 of output columns.
// ---------------------------------------------------------------------------
__global__ __launch_bounds__(256) void k_proj(const float* __restrict__ feat,
                                              const float* __restrict__ Wf,
                                              const float* __restrict__ bf,
                                              int N)
{
    __shared__ float sW[FDIM * DDIM];   // 16 KB, W_feat[f][d]
    __shared__ float sF[32][132];       // 32 rows x 128 feats, pad->132 (16B aligned, bank-skewed)
    __shared__ float sB[DDIM];

    for (int i = threadIdx.x; i < FDIM * DDIM; i += 256) sW[i] = Wf[i];
    if (threadIdx.x < DDIM) sB[threadIdx.x] = bf[threadIdx.x];

    const int lane = threadIdx.x & 31;
    const int warp = threadIdx.x >> 5;
    const int rin  = lane >> 3;         // 0..3 row within warp
    const int dq   = lane & 7;          // 0..7 -> d = dq*4 .. dq*4+3
    const int rl   = warp * 4 + rin;    // 0..31 row within tile

    const int ntiles = (N + 31) >> 5;
    for (int t = blockIdx.x; t < ntiles; t += gridDim.x) {
        const int rowbase = t << 5;
        __syncthreads();   // protect sF reuse (also covers initial weight load)
        for (int i = threadIdx.x; i < 32 * FDIM; i += 256) {
            int r = i >> 7, f = i & 127;
            int row = rowbase + r;
            sF[r][f] = (row < N) ? feat[row * FDIM + f] : 0.f;
        }
        __syncthreads();

        const int row = rowbase + rl;
        float4 a = make_float4(sB[dq * 4 + 0], sB[dq * 4 + 1],
                               sB[dq * 4 + 2], sB[dq * 4 + 3]);
        #pragma unroll
        for (int f0 = 0; f0 < FDIM; f0 += 4) {
            float4 fv = *(const float4*)&sF[rl][f0];
            const float* wp = &sW[f0 * DDIM + dq * 4];
            float4 w;
            w = *(const float4*)(wp);
            a.x = fmaf(fv.x, w.x, a.x); a.y = fmaf(fv.x, w.y, a.y);
            a.z = fmaf(fv.x, w.z, a.z); a.w = fmaf(fv.x, w.w, a.w);
            w = *(const float4*)(wp + DDIM);
            a.x = fmaf(fv.y, w.x, a.x); a.y = fmaf(fv.y, w.y, a.y);
            a.z = fmaf(fv.y, w.z, a.z); a.w = fmaf(fv.y, w.w, a.w);
            w = *(const float4*)(wp + 2 * DDIM);
            a.x = fmaf(fv.z, w.x, a.x); a.y = fmaf(fv.z, w.y, a.y);
            a.z = fmaf(fv.z, w.z, a.z); a.w = fmaf(fv.z, w.w, a.w);
            w = *(const float4*)(wp + 3 * DDIM);
            a.x = fmaf(fv.w, w.x, a.x); a.y = fmaf(fv.w, w.y, a.y);
            a.z = fmaf(fv.w, w.z, a.z); a.w = fmaf(fv.w, w.w, a.w);
        }
        if (row < N) {
            *(float4*)&g_proj[row * DDIM + dq * 4] = a;
            if ((lane & 7) == 0) g_skill[row] = (int)sF[rl][0];
        }
    }
}

// ---------------------------------------------------------------------------
// Kernel 2: one CTA per batch element b. Fuses:
//   gather proj over (r,l), skill-sim, mean over R, LayerNorm(D),
//   xW = hist @ W_gcn, chain-GCN message pass, relu(+b_gcn), mean over L,
//   src_emb = pool @ W_out + b_out ; dst_emb = proj[dst] @ W_out + b_out.
// Output layout: out[0 : B*D] = src_emb, out[B*D : 2*B*D] = dst_emb.
// ---------------------------------------------------------------------------
__global__ __launch_bounds__(256) void k_main(const int* __restrict__ rnodes,
    const int* __restrict__ ridx, const int* __restrict__ dst_ids,
    const float* __restrict__ wstr, const float* __restrict__ bstr,
    const float* __restrict__ lng, const float* __restrict__ lnb,
    const float* __restrict__ Wgcn, const float* __restrict__ bgcn,
    const float* __restrict__ Wout, const float* __restrict__ bout,
    float* __restrict__ out, int B)
{
    __shared__ float s_hist[LLEN][DDIM];   // 12.8 KB
    __shared__ float s_xW[LLEN][DDIM];     // 12.8 KB
    __shared__ float s_Wg[DDIM * DDIM];    // 4 KB
    __shared__ float s_Wo[DDIM * DDIM];    // 4 KB
    __shared__ float s_ws[DDIM], s_bs[DDIM], s_lg[DDIM], s_lb[DDIM];
    __shared__ float s_bg[DDIM], s_bo[DDIM];
    __shared__ float s_sum[DDIM];
    __shared__ float s_pre[DDIM], s_pre2[DDIM];
    __shared__ int   s_ridx[RNUM];
    __shared__ int   s_valid, s_cur, s_dst;

    const int b = blockIdx.x;
    const int tid = threadIdx.x, lane = tid & 31, warp = tid >> 5;

    for (int i = tid; i < DDIM * DDIM; i += 256) { s_Wg[i] = Wgcn[i]; s_Wo[i] = Wout[i]; }
    if (tid < DDIM) {
        s_ws[tid] = wstr[tid]; s_bs[tid] = bstr[tid];
        s_lg[tid] = lng[tid];  s_lb[tid] = lnb[tid];
        s_bg[tid] = bgcn[tid]; s_bo[tid] = bout[tid];
        s_sum[tid] = 0.f;
    }
    if (tid < RNUM) s_ridx[tid] = ridx[b * RNUM + tid];
    if (tid == 0) {
        int dn = dst_ids[b];
        s_dst = dn;
        s_cur = g_skill[dn];
        s_valid = 0;
    }
    __syncthreads();

    // valid[b] = sum_l (demo_nodes[b, 0, l] > 0)
    if (tid < LLEN) {
        int nd = rnodes[s_ridx[0] * LLEN + tid];
        if (nd > 0) atomicAdd(&s_valid, 1);
    }

    // hist rows: gather proj over R, add sim-Linear, mean over R, LayerNorm(D)
    const int cur = s_cur;
    for (int l = warp; l < LLEN; l += 8) {
        int nd = 0, sk = 0;
        if (lane < RNUM) {
            nd = rnodes[s_ridx[lane] * LLEN + l];
            sk = g_skill[nd];
        }
        float acc = 0.f, simc = 0.f;
        #pragma unroll
        for (int r = 0; r < RNUM; r++) {
            int ndr = __shfl_sync(0xffffffffu, nd, r);
            int skr = __shfl_sync(0xffffffffu, sk, r);
            acc += g_proj[ndr * DDIM + lane];
            simc += (skr == cur) ? 1.f : 0.f;
        }
        float h = (acc + simc * s_ws[lane]) * (1.f / RNUM) + s_bs[lane];

        float mu = h;
        #pragma unroll
        for (int o = 16; o > 0; o >>= 1) mu += __shfl_xor_sync(0xffffffffu, mu, o);
        mu *= (1.f / DDIM);
        float xm = h - mu;
        float v = xm * xm;
        #pragma unroll
        for (int o = 16; o > 0; o >>= 1) v += __shfl_xor_sync(0xffffffffu, v, o);
        v *= (1.f / DDIM);
        s_hist[l][lane] = xm * rsqrtf(v + 1e-5f) * s_lg[lane] + s_lb[lane];
    }
    __syncthreads();

    // xW = hist @ W_gcn
    for (int l = warp; l < LLEN; l += 8) {
        float acc = 0.f;
        #pragma unroll
        for (int k = 0; k < DDIM; k++)
            acc = fmaf(s_hist[l][k], s_Wg[k * DDIM + lane], acc);
        s_xW[l][lane] = acc;
    }
    __syncthreads();

    // chain GCN + relu + mean over L (accumulate per-warp, then shared atomics)
    const int valid = s_valid;
    float lsum = 0.f;
    for (int l = warp; l < LLEN; l += 8) {
        bool has_in = (l >= 1 && l < valid);         // edge (l-1)->l exists
        float degl = has_in ? 2.f : 1.f;             // deg[l] = 1 + indegree
        float o = s_xW[l][lane] / degl;
        if (has_in) {
            float degp = (l >= 2 && (l - 1) < valid) ? 2.f : 1.f;
            o += s_xW[l - 1][lane] * rsqrtf(degp * degl);
        }
        o += s_bg[lane];
        lsum += fmaxf(o, 0.f);
    }
    atomicAdd(&s_sum[lane], lsum);
    __syncthreads();

    if (warp == 0) {
        s_pre[lane] = s_sum[lane] * (1.f / LLEN);
    } else if (warp == 1) {
        s_pre2[lane] = g_proj[s_dst * DDIM + lane];  // dst_raw @ W_feat + b_feat
    }
    __syncthreads();

    if (warp == 0) {
        float e = s_bo[lane];
        #pragma unroll
        for (int k = 0; k < DDIM; k++) e = fmaf(s_pre[k], s_Wo[k * DDIM + lane], e);
        out[b * DDIM + lane] = e;                       // src_emb
    } else if (warp == 1) {
        float e = s_bo[lane];
        #pragma unroll
        for (int k = 0; k < DDIM; k++) e = fmaf(s_pre2[k], s_Wo[k * DDIM + lane], e);
        out[B * DDIM + b * DDIM + lane] = e;            // dst_emb
    }
}

extern "C" void kernel_launch(void* const* d_in, const int* in_sizes, int n_in,
                              void* d_out, int out_size)
{
    const float* feat   = (const float*)d_in[0];   // [N, 128]
    const int*   rnodes = (const int*)  d_in[1];   // [P, 100]
    const int*   ridx   = (const int*)  d_in[2];   // [B, 5]
    // d_in[3] src_node_ids: unused by the reference
    const int*   dst    = (const int*)  d_in[4];   // [B]
    // d_in[5] node_interact_times: unused
    const float* Wf = (const float*)d_in[6];
    const float* bf = (const float*)d_in[7];
    const float* ws = (const float*)d_in[8];
    const float* bs = (const float*)d_in[9];
    const float* lg = (const float*)d_in[10];
    const float* lb = (const float*)d_in[11];
    const float* Wg = (const float*)d_in[12];
    const float* bg = (const float*)d_in[13];
    const float* Wo = (const float*)d_in[14];
    const float* bo = (const float*)d_in[15];
    float* out = (float*)d_out;

    int N = in_sizes[0] / FDIM;
    int B = in_sizes[4];
    if (N > NMAX) N = NMAX;

    k_proj<<<592, 256>>>(feat, Wf, bf, N);
    k_main<<<B, 256>>>(rnodes, ridx, dst, ws, bs, lg, lb, Wg, bg, Wo, bo, out, B);
}

// round 4
// speedup vs baseline: 1.5201x; 1.5201x over previous
#include <cuda_runtime.h>
#include <cuda_bf16.h>

#define NMAX 100000
#define FDIM 128
#define DDIM 32
#define LLEN 100
#define RNUM 5

// Scratch (static device globals — no allocation in kernel_launch)
__device__ float g_proj[NMAX * DDIM];   // features @ W_feat + b_feat, per node
__device__ int   g_skill[NMAX];         // (int)features[n,0]

__device__ __forceinline__ void fma4(float4& acc, float s, const float4& wv) {
    acc.x = fmaf(s, wv.x, acc.x);
    acc.y = fmaf(s, wv.y, acc.y);
    acc.z = fmaf(s, wv.z, acc.z);
    acc.w = fmaf(s, wv.w, acc.w);
}

// ---------------------------------------------------------------------------
// Kernel 1: proj = feat @ W_feat + b_feat, skill = (int)feat[:,0].
// Thread computes 4 rows x 4 cols. Warp = 16 rows x 32 cols. CTA = 128 rows.
// Row data straight from gmem (L1 dedups the 8 lanes sharing a row);
// weights from smem. 8 LDS/LDG per 64 FMA, no syncs in the main loop.
// ---------------------------------------------------------------------------
__global__ __launch_bounds__(256) void k_proj(const float* __restrict__ feat,
                                              const float* __restrict__ Wf,
                                              const float* __restrict__ bf,
                                              int N)
{
    __shared__ __align__(16) float sW[FDIM * DDIM];   // 16 KB W_feat[f][d]
    __shared__ __align__(16) float sB[DDIM];

    for (int i = threadIdx.x; i < FDIM * DDIM; i += 256) sW[i] = Wf[i];
    if (threadIdx.x < DDIM) sB[threadIdx.x] = bf[threadIdx.x];
    __syncthreads();

    const int lane = threadIdx.x & 31;
    const int warp = threadIdx.x >> 5;
    const int dq   = lane & 7;          // col group: cols dq*4 .. dq*4+3
    const int rg   = lane >> 3;         // row group within warp
    const int rb   = (blockIdx.x * 8 + warp) * 16 + rg * 4;  // rows rb..rb+3
    if (rb >= N) return;

    // clamp row pointers (stores are guarded; loads stay in-bounds)
    const int r0 = rb,                 r1 = min(rb + 1, N - 1);
    const int r2 = min(rb + 2, N - 1), r3 = min(rb + 3, N - 1);
    const float* p0 = feat + (size_t)r0 * FDIM;
    const float* p1 = feat + (size_t)r1 * FDIM;
    const float* p2 = feat + (size_t)r2 * FDIM;
    const float* p3 = feat + (size_t)r3 * FDIM;

    if (dq == 0) {   // skill = truncating int cast of feature 0
        g_skill[r0] = (int)p0[0];
        if (rb + 1 < N) g_skill[r1] = (int)p1[0];
        if (rb + 2 < N) g_skill[r2] = (int)p2[0];
        if (rb + 3 < N) g_skill[r3] = (int)p3[0];
    }

    float4 bias = *(const float4*)&sB[dq * 4];
    float4 a0 = bias, a1 = bias, a2 = bias, a3 = bias;

    #pragma unroll 8
    for (int f0 = 0; f0 < FDIM; f0 += 4) {
        float4 x0 = *(const float4*)(p0 + f0);
        float4 x1 = *(const float4*)(p1 + f0);
        float4 x2 = *(const float4*)(p2 + f0);
        float4 x3 = *(const float4*)(p3 + f0);
        float4 w0 = *(const float4*)&sW[(f0 + 0) * DDIM + dq * 4];
        float4 w1 = *(const float4*)&sW[(f0 + 1) * DDIM + dq * 4];
        float4 w2 = *(const float4*)&sW[(f0 + 2) * DDIM + dq * 4];
        float4 w3 = *(const float4*)&sW[(f0 + 3) * DDIM + dq * 4];
        fma4(a0, x0.x, w0); fma4(a0, x0.y, w1); fma4(a0, x0.z, w2); fma4(a0, x0.w, w3);
        fma4(a1, x1.x, w0); fma4(a1, x1.y, w1); fma4(a1, x1.z, w2); fma4(a1, x1.w, w3);
        fma4(a2, x2.x, w0); fma4(a2, x2.y, w1); fma4(a2, x2.z, w2); fma4(a2, x2.w, w3);
        fma4(a3, x3.x, w0); fma4(a3, x3.y, w1); fma4(a3, x3.z, w2); fma4(a3, x3.w, w3);
    }

    *(float4*)&g_proj[(size_t)r0 * DDIM + dq * 4] = a0;
    if (rb + 1 < N) *(float4*)&g_proj[(size_t)r1 * DDIM + dq * 4] = a1;
    if (rb + 2 < N) *(float4*)&g_proj[(size_t)r2 * DDIM + dq * 4] = a2;
    if (rb + 3 < N) *(float4*)&g_proj[(size_t)r3 * DDIM + dq * 4] = a3;
}

// ---------------------------------------------------------------------------
// Kernel 2: one CTA per batch element. Stage node ids + skills into smem
// first (breaks the dependent address chains), then gather/LN/GCN/pool/out.
// Output: out[0:B*D] = src_emb, out[B*D:2*B*D] = dst_emb.
// ---------------------------------------------------------------------------
__global__ __launch_bounds__(256) void k_main(const int* __restrict__ rnodes,
    const int* __restrict__ ridx, const int* __restrict__ dst_ids,
    const float* __restrict__ wstr, const float* __restrict__ bstr,
    const float* __restrict__ lng, const float* __restrict__ lnb,
    const float* __restrict__ Wgcn, const float* __restrict__ bgcn,
    const float* __restrict__ Wout, const float* __restrict__ bout,
    float* __restrict__ out, int B)
{
    __shared__ int   s_nodes[RNUM * LLEN];                 // 2 KB
    __shared__ int   s_skill[RNUM * LLEN];                 // 2 KB
    __shared__ __align__(16) float s_hist[LLEN][DDIM];     // 12.8 KB
    __shared__ __align__(16) float s_xW[LLEN][DDIM];       // 12.8 KB
    __shared__ float s_ws[DDIM], s_bs[DDIM], s_lg[DDIM], s_lb[DDIM], s_bg[DDIM];
    __shared__ float s_part[8][DDIM];                      // per-warp pool partials
    __shared__ int   s_ridx[RNUM];
    __shared__ int   s_cur, s_dst;

    const int b = blockIdx.x;
    const int tid = threadIdx.x, lane = tid & 31, warp = tid >> 5;

    if (tid < DDIM) {
        s_ws[tid] = wstr[tid]; s_bs[tid] = bstr[tid];
        s_lg[tid] = lng[tid];  s_lb[tid] = lnb[tid];
        s_bg[tid] = bgcn[tid];
    }
    if (tid < RNUM) s_ridx[tid] = ridx[b * RNUM + tid];
    if (tid == 0) {
        int dn = dst_ids[b];
        s_dst = dn;
        s_cur = g_skill[dn];
    }
    __syncthreads();

    // stage node ids (coalesced-ish: 100 consecutive per retrieved row)
    for (int i = tid; i < RNUM * LLEN; i += 256) {
        int r = i / LLEN, c = i - r * LLEN;
        s_nodes[i] = rnodes[s_ridx[r] * LLEN + c];
    }
    __syncthreads();

    // stage skills (independent scattered loads, high MLP)
    for (int i = tid; i < RNUM * LLEN; i += 256)
        s_skill[i] = g_skill[s_nodes[i]];

    // valid[b] = count of demo_nodes[b,0,l] > 0  (also the barrier for s_skill)
    const int valid = __syncthreads_count(tid < LLEN && s_nodes[tid] > 0);

    // hist: gather proj over R (5 independent 128B loads), sim, mean, LayerNorm
    const int cur = s_cur;
    for (int l = warp; l < LLEN; l += 8) {
        float acc = 0.f, sim = 0.f;
        #pragma unroll
        for (int r = 0; r < RNUM; r++) {
            int nd = s_nodes[r * LLEN + l];
            acc += g_proj[(size_t)nd * DDIM + lane];
            sim += (s_skill[r * LLEN + l] == cur) ? 1.f : 0.f;
        }
        float h = (acc + sim * s_ws[lane]) * (1.f / RNUM) + s_bs[lane];

        float mu = h;
        #pragma unroll
        for (int o = 16; o > 0; o >>= 1) mu += __shfl_xor_sync(0xffffffffu, mu, o);
        mu *= (1.f / DDIM);
        float xm = h - mu;
        float v = xm * xm;
        #pragma unroll
        for (int o = 16; o > 0; o >>= 1) v += __shfl_xor_sync(0xffffffffu, v, o);
        v *= (1.f / DDIM);
        s_hist[l][lane] = xm * rsqrtf(v + 1e-5f) * s_lg[lane] + s_lb[lane];
    }
    __syncthreads();

    // xW = hist @ W_gcn, with this lane's W_gcn column held in registers
    {
        float wg[DDIM];
        #pragma unroll
        for (int k = 0; k < DDIM; k++) wg[k] = Wgcn[k * DDIM + lane];
        for (int l = warp; l < LLEN; l += 8) {
            float acc = 0.f;
            #pragma unroll
            for (int k0 = 0; k0 < DDIM; k0 += 4) {
                float4 hv = *(const float4*)&s_hist[l][k0];  // warp broadcast
                acc = fmaf(hv.x, wg[k0 + 0], acc);
                acc = fmaf(hv.y, wg[k0 + 1], acc);
                acc = fmaf(hv.z, wg[k0 + 2], acc);
                acc = fmaf(hv.w, wg[k0 + 3], acc);
            }
            s_xW[l][lane] = acc;
        }
    }
    __syncthreads();

    // chain GCN + relu + mean over L (per-warp partials, deterministic reduce)
    float lsum = 0.f;
    for (int l = warp; l < LLEN; l += 8) {
        bool has_in = (l >= 1 && l < valid);          // edge (l-1)->l exists
        float o = s_xW[l][lane];
        if (has_in) {
            float degp = (l >= 2 && (l - 1) < valid) ? 2.f : 1.f;
            o = o * 0.5f + s_xW[l - 1][lane] * rsqrtf(degp * 2.f);
        }
        lsum += fmaxf(o + s_bg[lane], 0.f);
    }
    s_part[warp][lane] = lsum;
    __syncthreads();

    if (warp == 0) {
        float p = 0.f;
        #pragma unroll
        for (int w = 0; w < 8; w++) p += s_part[w][lane];
        p *= (1.f / LLEN);
        float wo[DDIM];
        #pragma unroll
        for (int k = 0; k < DDIM; k++) wo[k] = Wout[k * DDIM + lane];
        float e = bout[lane];
        #pragma unroll
        for (int k = 0; k < DDIM; k++) {
            float pk = __shfl_sync(0xffffffffu, p, k);
            e = fmaf(pk, wo[k], e);
        }
        out[b * DDIM + lane] = e;                      // src_emb
    } else if (warp == 1) {
        float p = g_proj[(size_t)s_dst * DDIM + lane];
        float wo[DDIM];
        #pragma unroll
        for (int k = 0; k < DDIM; k++) wo[k] = Wout[k * DDIM + lane];
        float e = bout[lane];
        #pragma unroll
        for (int k = 0; k < DDIM; k++) {
            float pk = __shfl_sync(0xffffffffu, p, k);
            e = fmaf(pk, wo[k], e);
        }
        out[B * DDIM + b * DDIM + lane] = e;           // dst_emb
    }
}

extern "C" void kernel_launch(void* const* d_in, const int* in_sizes, int n_in,
                              void* d_out, int out_size)
{
    const float* feat   = (const float*)d_in[0];   // [N, 128]
    const int*   rnodes = (const int*)  d_in[1];   // [P, 100]
    const int*   ridx   = (const int*)  d_in[2];   // [B, 5]
    const int*   dst    = (const int*)  d_in[4];   // [B]
    const float* Wf = (const float*)d_in[6];
    const float* bf = (const float*)d_in[7];
    const float* ws = (const float*)d_in[8];
    const float* bs = (const float*)d_in[9];
    const float* lg = (const float*)d_in[10];
    const float* lb = (const float*)d_in[11];
    const float* Wg = (const float*)d_in[12];
    const float* bg = (const float*)d_in[13];
    const float* Wo = (const float*)d_in[14];
    const float* bo = (const float*)d_in[15];
    float* out = (float*)d_out;

    int N = in_sizes[0] / FDIM;
    int B = in_sizes[4];
    if (N > NMAX) N = NMAX;

    int nblk = (N + 127) / 128;
    k_proj<<<nblk, 256>>>(feat, Wf, bf, N);
    k_main<<<B, 256>>>(rnodes, ridx, dst, ws, bs, lg, lb, Wg, bg, Wo, bo, out, B);
}